// round 2
// baseline (speedup 1.0000x reference)
#include <cuda_runtime.h>
#include <cstdint>

// Problem constants (fixed by the reference: B=64, S=512, H=768)
#define PB 64
#define PS 512
#define PH 768
#define NTOK (PB * PS)                       // 32768 tokens
#define SPAN ((size_t)PB * PS * PS)          // 16,777,216 elements per output tensor

// Per-token scratch (device globals: allocation-free, graph-capturable)
__device__ float         g_a[NTOK];
__device__ float         g_c[NTOK];
__device__ unsigned char g_sc[NTOK];
__device__ unsigned char g_ec[NTOK];

// ---------------------------------------------------------------------------
// Kernel 1: per-token fused matvecs, register-resident weights.
// Warp PAIR per token: even warp computes (start-logit-diff, a), odd warp
// computes (end-logit-diff, c). Each warp keeps its two weight vectors
// (12 float4 per lane) in registers, loaded once; tokens processed in a
// grid-stride loop so the load is amortized. No shared memory in the loop.
// ---------------------------------------------------------------------------
__global__ __launch_bounds__(256) void token_kernel(
    const float* __restrict__ rep,
    const int*   __restrict__ mask,
    const float* __restrict__ W_start,
    const float* __restrict__ b_start,
    const float* __restrict__ W_end,
    const float* __restrict__ b_end,
    const float* __restrict__ W_m,
    const float* __restrict__ b_m)
{
    const int tid  = threadIdx.x;
    const int warp = tid >> 5;
    const int lane = tid & 31;
    const int pair = warp >> 1;        // 0..3 : token slot within block
    const int side = warp & 1;         // 0: start/a, 1: end/c

    // Load this warp's weight slices into registers (once).
    float4 wd[6];   // logit-difference weights (start or end)
    float4 wm[6];   // W_m[:H] (side 0) or W_m[H:] (side 1)
    const float* Wse = side ? W_end : W_start;
    const float* Wmh = W_m + (side ? PH : 0);
    #pragma unroll
    for (int k = 0; k < 6; ++k) {
        const int h = (lane + k * 32) * 4;     // element base index
        float4 w;
        w.x = Wse[(h + 0) * 2 + 1] - Wse[(h + 0) * 2];
        w.y = Wse[(h + 1) * 2 + 1] - Wse[(h + 1) * 2];
        w.z = Wse[(h + 2) * 2 + 1] - Wse[(h + 2) * 2];
        w.w = Wse[(h + 3) * 2 + 1] - Wse[(h + 3) * 2];
        wd[k] = w;
        wm[k] = *reinterpret_cast<const float4*>(Wmh + h);
    }
    const float biasd = side ? (b_end[1] - b_end[0]) : (b_start[1] - b_start[0]);
    const float bm    = b_m[0];

    // Grid-stride over tokens: each block advances 4 tokens per iteration.
    for (int token = blockIdx.x * 4 + pair; token < NTOK; token += gridDim.x * 4) {
        const float4* r4 = reinterpret_cast<const float4*>(rep + (size_t)token * PH);

        float d = 0.f, v = 0.f;
        #pragma unroll
        for (int k = 0; k < 6; ++k) {
            const float4 r = r4[lane + k * 32];
            d += r.x * wd[k].x + r.y * wd[k].y + r.z * wd[k].z + r.w * wd[k].w;
            v += r.x * wm[k].x + r.y * wm[k].y + r.z * wm[k].z + r.w * wm[k].w;
        }
        #pragma unroll
        for (int off = 16; off > 0; off >>= 1) {
            d += __shfl_down_sync(0xFFFFFFFFu, d, off);
            v += __shfl_down_sync(0xFFFFFFFFu, v, off);
        }
        if (lane == 0) {
            const int valid = (mask[token] != 0);
            const unsigned char cand = (unsigned char)(valid && (d + biasd >= 0.f));
            if (side == 0) {
                g_sc[token] = cand;
                g_a[token]  = v + bm;
            } else {
                g_ec[token] = cand;
                g_c[token]  = v;
            }
        }
    }
}

// ---------------------------------------------------------------------------
// Kernel 2: span materialization, register-cached c-row.
// One block per (b, 32-row tile). Each thread owns a fixed 4-wide e-slice:
// c4/ec4 are loaded ONCE into registers and reused across all 32 s-rows.
// 256 threads process 2 rows concurrently (128 threads x float4 per row).
//   scores[b,s,e] = a[b,s] + c[b,e]
//   mask = start_cand[b,s] & end_cand[b,e] & (s<=e) & (score>0)
// ---------------------------------------------------------------------------
#define ROWS_PER_BLK 32
__global__ __launch_bounds__(256) void span_kernel(float* __restrict__ out)
{
    const int b    = blockIdx.x >> 4;                 // / (S/ROWS_PER_BLK) = /16
    const int s0   = (blockIdx.x & 15) * ROWS_PER_BLK;
    const int half = threadIdx.x >> 7;                // 0/1: which row of the pair
    const int e0   = (threadIdx.x & 127) << 2;        // fixed 4-wide e-slice

    const float4 c4  = *reinterpret_cast<const float4*>(g_c  + (b << 9) + e0);
    const uchar4 ec4 = *reinterpret_cast<const uchar4*>(g_ec + (b << 9) + e0);
    const float ecx = ec4.x ? 1.f : 0.f;
    const float ecy = ec4.y ? 1.f : 0.f;
    const float ecz = ec4.z ? 1.f : 0.f;
    const float ecw = ec4.w ? 1.f : 0.f;

    #pragma unroll 4
    for (int r = half; r < ROWS_PER_BLK; r += 2) {
        const int s  = s0 + r;
        const int bs = (b << 9) + s;
        const float a  = g_a[bs];
        const float sc = g_sc[bs] ? 1.f : 0.f;

        float4 sv;
        sv.x = a + c4.x;
        sv.y = a + c4.y;
        sv.z = a + c4.z;
        sv.w = a + c4.w;

        float4 mv;
        mv.x = (e0 + 0 >= s && sv.x > 0.f) ? sc * ecx : 0.f;
        mv.y = (e0 + 1 >= s && sv.y > 0.f) ? sc * ecy : 0.f;
        mv.z = (e0 + 2 >= s && sv.z > 0.f) ? sc * ecz : 0.f;
        mv.w = (e0 + 3 >= s && sv.w > 0.f) ? sc * ecw : 0.f;

        const size_t off = (size_t)bs * PS + e0;
        *reinterpret_cast<float4*>(out + off)        = mv;   // span_mask
        *reinterpret_cast<float4*>(out + SPAN + off) = sv;   // scores
    }
}

// ---------------------------------------------------------------------------
extern "C" void kernel_launch(void* const* d_in, const int* in_sizes, int n_in,
                              void* d_out, int out_size)
{
    const float* rep     = (const float*)d_in[0];   // [B,S,H] fp32
    const int*   mask    = (const int*)  d_in[1];   // [B,S]  int32
    const float* W_start = (const float*)d_in[2];   // [H,2]
    const float* b_start = (const float*)d_in[3];   // [2]
    const float* W_end   = (const float*)d_in[4];   // [H,2]
    const float* b_end   = (const float*)d_in[5];   // [2]
    const float* W_m     = (const float*)d_in[6];   // [2H]
    const float* b_m     = (const float*)d_in[7];   // scalar
    float* out = (float*)d_out;                     // [mask | scores], each B*S*S fp32

    // Kernel 1: 1024 blocks x 256 threads; 4 tokens per block-iteration,
    // 8 grid-stride iterations (32768 tokens total).
    token_kernel<<<1024, 256>>>(rep, mask, W_start, b_start, W_end, b_end, W_m, b_m);

    // Kernel 2: 64 batches x 16 row-tiles = 1024 blocks x 256 threads.
    span_kernel<<<PB * (PS / ROWS_PER_BLK), 256>>>(out);
}

// round 3
// speedup vs baseline: 1.4526x; 1.4526x over previous
#include <cuda_runtime.h>
#include <cstdint>

// Problem constants (fixed by the reference: B=64, S=512, H=768)
#define PB 64
#define PS 512
#define PH 768
#define NTOK (PB * PS)                       // 32768 tokens
#define SPAN ((size_t)PB * PS * PS)          // 16,777,216 elements per output tensor

// Per-token scratch (device globals: allocation-free, graph-capturable)
__device__ float         g_a[NTOK];
__device__ float         g_c[NTOK];
__device__ unsigned char g_sc[NTOK];
__device__ unsigned char g_ec[NTOK];

// ---------------------------------------------------------------------------
// Kernel 1: per-token fused matvecs, ALL weights register-resident.
// One warp per token computes all 4 dot products, so rep is read exactly once
// (6 x LDG.128 per token) with zero shared-memory traffic in the loop.
// 24 weight float4 (96 regs) loaded once per warp, amortized over a
// grid-stride token loop (~14 tokens/warp at grid=296).
// ---------------------------------------------------------------------------
__global__ void __launch_bounds__(256) token_kernel(
    const float* __restrict__ rep,
    const int*   __restrict__ mask,
    const float* __restrict__ W_start,
    const float* __restrict__ b_start,
    const float* __restrict__ W_end,
    const float* __restrict__ b_end,
    const float* __restrict__ W_m,
    const float* __restrict__ b_m)
{
    const int warp = threadIdx.x >> 5;
    const int lane = threadIdx.x & 31;

    // Load all 4 weight vectors' lane-slices into registers (once per warp).
    float4 ws[6], we[6], wa[6], wc[6];
    #pragma unroll
    for (int k = 0; k < 6; ++k) {
        const int h = (lane + k * 32) * 4;
        float4 t;
        t.x = W_start[(h + 0) * 2 + 1] - W_start[(h + 0) * 2];
        t.y = W_start[(h + 1) * 2 + 1] - W_start[(h + 1) * 2];
        t.z = W_start[(h + 2) * 2 + 1] - W_start[(h + 2) * 2];
        t.w = W_start[(h + 3) * 2 + 1] - W_start[(h + 3) * 2];
        ws[k] = t;
        t.x = W_end[(h + 0) * 2 + 1] - W_end[(h + 0) * 2];
        t.y = W_end[(h + 1) * 2 + 1] - W_end[(h + 1) * 2];
        t.z = W_end[(h + 2) * 2 + 1] - W_end[(h + 2) * 2];
        t.w = W_end[(h + 3) * 2 + 1] - W_end[(h + 3) * 2];
        we[k] = t;
        wa[k] = *reinterpret_cast<const float4*>(W_m + h);
        wc[k] = *reinterpret_cast<const float4*>(W_m + PH + h);
    }
    const float bsd = b_start[1] - b_start[0];
    const float bed = b_end[1]   - b_end[0];
    const float bm  = b_m[0];

    const int warp0 = blockIdx.x * 8 + warp;
    const int nwarp = gridDim.x * 8;

    for (int token = warp0; token < NTOK; token += nwarp) {
        const float4* r4 = reinterpret_cast<const float4*>(rep + (size_t)token * PH);

        float ds = 0.f, de = 0.f, va = 0.f, vc = 0.f;
        #pragma unroll
        for (int k = 0; k < 6; ++k) {
            const float4 r = r4[lane + k * 32];
            ds += r.x * ws[k].x + r.y * ws[k].y + r.z * ws[k].z + r.w * ws[k].w;
            de += r.x * we[k].x + r.y * we[k].y + r.z * we[k].z + r.w * we[k].w;
            va += r.x * wa[k].x + r.y * wa[k].y + r.z * wa[k].z + r.w * wa[k].w;
            vc += r.x * wc[k].x + r.y * wc[k].y + r.z * wc[k].z + r.w * wc[k].w;
        }
        #pragma unroll
        for (int off = 16; off > 0; off >>= 1) {
            ds += __shfl_down_sync(0xFFFFFFFFu, ds, off);
            de += __shfl_down_sync(0xFFFFFFFFu, de, off);
            va += __shfl_down_sync(0xFFFFFFFFu, va, off);
            vc += __shfl_down_sync(0xFFFFFFFFu, vc, off);
        }
        if (lane == 0) {
            const int valid = (mask[token] != 0);
            g_sc[token] = (unsigned char)(valid && (ds + bsd >= 0.f));
            g_ec[token] = (unsigned char)(valid && (de + bed >= 0.f));
            g_a[token]  = va + bm;
            g_c[token]  = vc;
        }
    }
}

// ---------------------------------------------------------------------------
// Kernel 2: span materialization, register-cached c-row + streaming stores.
// One block per (b, 16-row tile). Each thread owns a fixed 4-wide e-slice:
// c4/ec4 loaded ONCE into registers, reused across the 16 s-rows. Output is
// never re-read, so use __stcs (evict-first) to keep it out of L2's way.
//   scores[b,s,e] = a[b,s] + c[b,e]
//   mask = start_cand[b,s] & end_cand[b,e] & (s<=e) & (score>0)
// ---------------------------------------------------------------------------
#define ROWS_PER_BLK 16
__global__ void __launch_bounds__(256) span_kernel(float* __restrict__ out)
{
    const int b    = blockIdx.x >> 5;                 // / (S/ROWS_PER_BLK) = /32
    const int s0   = (blockIdx.x & 31) * ROWS_PER_BLK;
    const int half = threadIdx.x >> 7;                // 0/1: which row of the pair
    const int e0   = (threadIdx.x & 127) << 2;        // fixed 4-wide e-slice

    const float4 c4  = *reinterpret_cast<const float4*>(g_c  + (b << 9) + e0);
    const uchar4 ec4 = *reinterpret_cast<const uchar4*>(g_ec + (b << 9) + e0);
    const float ecx = ec4.x ? 1.f : 0.f;
    const float ecy = ec4.y ? 1.f : 0.f;
    const float ecz = ec4.z ? 1.f : 0.f;
    const float ecw = ec4.w ? 1.f : 0.f;

    #pragma unroll
    for (int r = half; r < ROWS_PER_BLK; r += 2) {
        const int s  = s0 + r;
        const int bs = (b << 9) + s;
        const float a  = g_a[bs];
        const float sc = g_sc[bs] ? 1.f : 0.f;

        float4 sv;
        sv.x = a + c4.x;
        sv.y = a + c4.y;
        sv.z = a + c4.z;
        sv.w = a + c4.w;

        float4 mv;
        mv.x = (e0 + 0 >= s && sv.x > 0.f) ? sc * ecx : 0.f;
        mv.y = (e0 + 1 >= s && sv.y > 0.f) ? sc * ecy : 0.f;
        mv.z = (e0 + 2 >= s && sv.z > 0.f) ? sc * ecz : 0.f;
        mv.w = (e0 + 3 >= s && sv.w > 0.f) ? sc * ecw : 0.f;

        const size_t off = (size_t)bs * PS + e0;
        __stcs(reinterpret_cast<float4*>(out + off),        mv);   // span_mask
        __stcs(reinterpret_cast<float4*>(out + SPAN + off), sv);   // scores
    }
}

// ---------------------------------------------------------------------------
extern "C" void kernel_launch(void* const* d_in, const int* in_sizes, int n_in,
                              void* d_out, int out_size)
{
    const float* rep     = (const float*)d_in[0];   // [B,S,H] fp32
    const int*   mask    = (const int*)  d_in[1];   // [B,S]  int32
    const float* W_start = (const float*)d_in[2];   // [H,2]
    const float* b_start = (const float*)d_in[3];   // [2]
    const float* W_end   = (const float*)d_in[4];   // [H,2]
    const float* b_end   = (const float*)d_in[5];   // [2]
    const float* W_m     = (const float*)d_in[6];   // [2H]
    const float* b_m     = (const float*)d_in[7];   // scalar
    float* out = (float*)d_out;                     // [mask | scores], each B*S*S fp32

    // Kernel 1: 296 blocks x 8 warps = one full wave at 2 blocks/SM;
    // each warp grid-strides ~14 tokens with register-resident weights.
    token_kernel<<<296, 256>>>(rep, mask, W_start, b_start, W_end, b_end, W_m, b_m);

    // Kernel 2: 64 batches x 32 row-tiles = 2048 blocks x 256 threads.
    span_kernel<<<PB * (PS / ROWS_PER_BLK), 256>>>(out);
}